// round 1
// baseline (speedup 1.0000x reference)
#include <cuda_runtime.h>
#include <math.h>

// ---------------- problem constants ----------------
#define BATCH   8
#define HH      36
#define WW      100
#define N_TOT   28800          // 8*36*100
#define K1      4608           // 512*9
#define M1      1024
#define K2      1024
#define M2      128
#define SEG_ELEMS (8*5*288*800)   // 9,216,000

// ---------------- device scratch (static globals; no allocation) ----------------
__device__ float g_wp1[K1 * M1];     // conv1a weights packed [k'][m], k' = tap*512 + c
__device__ float g_wp2[K2 * M2];     // conv1b weights packed [k][m]
__device__ float g_h1[M1 * N_TOT];   // stage-1 activations, layout [c][b*3600+h*100+w]
__device__ float g_h2[M2 * N_TOT];   // stage-2 activations, same layout
__device__ float g_h3[5 * N_TOT];    // logits
__device__ float g_p[8 * 4500];      // pooled softmax features
// ---------------------------------------------------

// Pack weights: wp1[(tap*512+c)*1024 + m] = w1a[m][c][tap]; wp2[k*128+m] = w1b[m][k]
__global__ void pack_w(const float* __restrict__ w1a, const float* __restrict__ w1b) {
    int o = blockIdx.x * blockDim.x + threadIdx.x;
    if (o < K1 * M1) {
        int m   = o & 1023;
        int kp  = o >> 10;           // k' = tap*512 + c
        int c   = kp & 511;
        int tap = kp >> 9;
        g_wp1[o] = w1a[(m * 512 + c) * 9 + tap];
    }
    if (o < K2 * M2) {
        int m = o & 127;
        int k = o >> 7;
        g_wp2[o] = w1b[m * 1024 + k];
    }
}

// ---------------- conv1a: dilated 3x3 implicit GEMM, fused BN1+ReLU ----------------
// grid (225, 8), block 256.  C[m][n] -> g_h1
__global__ __launch_bounds__(256, 2)
void conv1a_k(const float* __restrict__ x,
              const float* __restrict__ bg, const float* __restrict__ bb,
              const float* __restrict__ bm, const float* __restrict__ bv) {
    __shared__ float4 As4[16][32];
    __shared__ float4 Bs4[16][32];
    float* Bs = (float*)Bs4;

    int tid = threadIdx.x;
    int n0 = blockIdx.x * 128;
    int m0 = blockIdx.y * 128;

    // per-thread B-loader slot: nn fixed, kk = kkb + 2*i
    int nn  = tid & 127;
    int kkb = tid >> 7;
    int n = n0 + nn;
    int b = n / 3600; int r = n - b * 3600;
    int h = r / 100;  int w = r - h * 100;
    const float* xb = x + b * 512 * 3600;

    float acc[8][8];
#pragma unroll
    for (int i = 0; i < 8; i++)
#pragma unroll
        for (int j = 0; j < 8; j++) acc[i][j] = 0.f;

    int tm2 = (tid >> 4) * 2;
    int tn2 = (tid & 15) * 2;

    int  boff = 0;
    bool valid = false;

    for (int k0 = 0; k0 < K1; k0 += 16) {
        if ((k0 & 511) == 0) {        // new tap block
            int tap = k0 >> 9;
            int kh = tap / 3, kw = tap - kh * 3;
            int ih = h + 4 * kh - 4;
            int iw = w + 4 * kw - 4;
            valid = ((unsigned)ih < 36u) && ((unsigned)iw < 100u);
            boff  = ih * 100 + iw;
        }
        int cb = k0 & 511;

        // load A tile (coalesced float4 from packed weights)
#pragma unroll
        for (int i = 0; i < 2; i++) {
            int idx = tid + i * 256;
            int kk = idx >> 5, m4 = idx & 31;
            As4[kk][m4] = *(const float4*)&g_wp1[(k0 + kk) * 1024 + m0 + m4 * 4];
        }
        // load B tile (implicit im2col gather: 1 IMAD + LDG per element)
#pragma unroll
        for (int i = 0; i < 8; i++) {
            int kk = kkb + 2 * i;
            float v = 0.f;
            if (valid) v = __ldg(&xb[(cb + kk) * 3600 + boff]);
            Bs[kk * 128 + nn] = v;
        }
        __syncthreads();

#pragma unroll
        for (int kk = 0; kk < 16; kk++) {
            float av[8], bvx[8];
            *(float4*)&av[0]  = As4[kk][tm2];
            *(float4*)&av[4]  = As4[kk][tm2 + 1];
            *(float4*)&bvx[0] = Bs4[kk][tn2];
            *(float4*)&bvx[4] = Bs4[kk][tn2 + 1];
#pragma unroll
            for (int mi = 0; mi < 8; mi++)
#pragma unroll
                for (int ni = 0; ni < 8; ni++)
                    acc[mi][ni] = fmaf(av[mi], bvx[ni], acc[mi][ni]);
        }
        __syncthreads();
    }

    // epilogue: BN1 + ReLU
    int rm = (tid >> 4) * 8;
    int rn = (tid & 15) * 8;
#pragma unroll
    for (int mi = 0; mi < 8; mi++) {
        int m = m0 + rm + mi;
        float s  = bg[m] * rsqrtf(bv[m] + 1e-5f);
        float sh = bb[m] - bm[m] * s;
        float o[8];
#pragma unroll
        for (int ni = 0; ni < 8; ni++)
            o[ni] = fmaxf(acc[mi][ni] * s + sh, 0.f);
        float* dst = &g_h1[m * N_TOT + n0 + rn];
        *(float4*)&dst[0] = *(float4*)&o[0];
        *(float4*)&dst[4] = *(float4*)&o[4];
    }
}

// ---------------- conv1b: 1x1 GEMM (128x28800 = W[128x1024] * h1), fused BN2+ReLU ----------------
// grid (225), block 256
__global__ __launch_bounds__(256, 2)
void conv1b_k(const float* __restrict__ bg, const float* __restrict__ bb,
              const float* __restrict__ bm, const float* __restrict__ bv) {
    __shared__ float4 As4[16][32];
    __shared__ float4 Bs4[16][32];
    float* Bs = (float*)Bs4;

    int tid = threadIdx.x;
    int n0 = blockIdx.x * 128;
    int nn  = tid & 127;
    int kkb = tid >> 7;

    float acc[8][8];
#pragma unroll
    for (int i = 0; i < 8; i++)
#pragma unroll
        for (int j = 0; j < 8; j++) acc[i][j] = 0.f;

    int tm2 = (tid >> 4) * 2;
    int tn2 = (tid & 15) * 2;

    for (int k0 = 0; k0 < K2; k0 += 16) {
#pragma unroll
        for (int i = 0; i < 2; i++) {
            int idx = tid + i * 256;
            int kk = idx >> 5, m4 = idx & 31;
            As4[kk][m4] = *(const float4*)&g_wp2[(k0 + kk) * 128 + m4 * 4];
        }
#pragma unroll
        for (int i = 0; i < 8; i++) {
            int kk = kkb + 2 * i;
            Bs[kk * 128 + nn] = g_h1[(k0 + kk) * N_TOT + n0 + nn];
        }
        __syncthreads();
#pragma unroll
        for (int kk = 0; kk < 16; kk++) {
            float av[8], bvx[8];
            *(float4*)&av[0]  = As4[kk][tm2];
            *(float4*)&av[4]  = As4[kk][tm2 + 1];
            *(float4*)&bvx[0] = Bs4[kk][tn2];
            *(float4*)&bvx[4] = Bs4[kk][tn2 + 1];
#pragma unroll
            for (int mi = 0; mi < 8; mi++)
#pragma unroll
                for (int ni = 0; ni < 8; ni++)
                    acc[mi][ni] = fmaf(av[mi], bvx[ni], acc[mi][ni]);
        }
        __syncthreads();
    }

    int rm = (tid >> 4) * 8;
    int rn = (tid & 15) * 8;
#pragma unroll
    for (int mi = 0; mi < 8; mi++) {
        int m = rm + mi;
        float s  = bg[m] * rsqrtf(bv[m] + 1e-5f);
        float sh = bb[m] - bm[m] * s;
        float o[8];
#pragma unroll
        for (int ni = 0; ni < 8; ni++)
            o[ni] = fmaxf(acc[mi][ni] * s + sh, 0.f);
        float* dst = &g_h2[m * N_TOT + n0 + rn];
        *(float4*)&dst[0] = *(float4*)&o[0];
        *(float4*)&dst[4] = *(float4*)&o[4];
    }
}

// ---------------- message passing: one step along H-scan (conv over W, len 100) ----------------
// grid (8, 16), block 256 = 8 c_out x 32 pos-chunks of 4
__global__ __launch_bounds__(256)
void step_w(const float* __restrict__ wgt, int h_prev, int h_cur) {
    __shared__ float sp[64 * 108];   // half the channels at a time (fits 48KB static)
    int b  = blockIdx.x;
    int cg = blockIdx.y;
    int tid = threadIdx.x;
    int tx = tid & 31, ty = tid >> 5;
    int p0 = tx * 4;
    int co = cg * 8 + ty;

    float acc[4] = {0.f, 0.f, 0.f, 0.f};
    const float* prevBase = g_h2 + b * 3600 + h_prev * 100;

    for (int half = 0; half < 2; half++) {
        for (int idx = tid; idx < 64 * 108; idx += 256) {
            int ci = idx / 108;
            int p  = idx - ci * 108 - 4;
            sp[idx] = ((unsigned)p < 100u) ? prevBase[(half * 64 + ci) * N_TOT + p] : 0.f;
        }
        __syncthreads();
        if (p0 < 100) {
            const float* wrow = wgt + (co * 128 + half * 64) * 9;
            const float4* sp4 = (const float4*)sp;
            for (int ci = 0; ci < 64; ci++) {
                float4 A  = sp4[ci * 27 + tx];
                float4 Bq = sp4[ci * 27 + tx + 1];
                float4 C  = sp4[ci * 27 + tx + 2];
                float v[12] = {A.x, A.y, A.z, A.w, Bq.x, Bq.y, Bq.z, Bq.w, C.x, C.y, C.z, C.w};
                float wv[9];
#pragma unroll
                for (int t = 0; t < 9; t++) wv[t] = __ldg(&wrow[ci * 9 + t]);
#pragma unroll
                for (int q = 0; q < 4; q++)
#pragma unroll
                    for (int t = 0; t < 9; t++)
                        acc[q] = fmaf(wv[t], v[q + t], acc[q]);
            }
        }
        __syncthreads();
    }
    if (p0 < 100) {
        float* cur = g_h2 + co * N_TOT + b * 3600 + h_cur * 100 + p0;
#pragma unroll
        for (int q = 0; q < 4; q++)
            cur[q] += fmaxf(acc[q], 0.f);
    }
}

// ---------------- message passing: one step along W-scan (conv over H, len 36) ----------------
// grid (8, 16), block 128 = 8 c_out x 16 pos-chunks of 3
__global__ __launch_bounds__(128)
void step_h(const float* __restrict__ wgt, int w_prev, int w_cur) {
    __shared__ float sp[128 * 44];
    int b  = blockIdx.x;
    int cg = blockIdx.y;
    int tid = threadIdx.x;

    for (int idx = tid; idx < 128 * 44; idx += 128) {
        int ci = idx / 44;
        int p  = idx - ci * 44 - 4;
        sp[idx] = ((unsigned)p < 36u) ? g_h2[ci * N_TOT + b * 3600 + p * 100 + w_prev] : 0.f;
    }
    __syncthreads();

    int tx = tid & 15, ty = tid >> 4;
    int p0 = tx * 3;
    if (p0 < 36) {
        int co = cg * 8 + ty;
        const float* wrow = wgt + co * 1152;
        float acc[3] = {0.f, 0.f, 0.f};
        for (int ci = 0; ci < 128; ci++) {
            const float* s = sp + ci * 44 + p0;   // s[j] = pos (p0-4+j)
            float v[11];
#pragma unroll
            for (int j = 0; j < 11; j++) v[j] = s[j];
            float wv[9];
#pragma unroll
            for (int t = 0; t < 9; t++) wv[t] = __ldg(&wrow[ci * 9 + t]);
#pragma unroll
            for (int q = 0; q < 3; q++)
#pragma unroll
                for (int t = 0; t < 9; t++)
                    acc[q] = fmaf(wv[t], v[q + t], acc[q]);
        }
        float* cur = g_h2 + co * N_TOT + b * 3600 + p0 * 100 + w_cur;
#pragma unroll
        for (int q = 0; q < 3; q++)
            cur[q * 100] += fmaxf(acc[q], 0.f);
    }
}

// ---------------- conv2: 1x1 128->5 + bias ----------------
__global__ void conv2_k(const float* __restrict__ w2, const float* __restrict__ b2) {
    int n = blockIdx.x * blockDim.x + threadIdx.x;
    if (n >= N_TOT) return;
    float acc[5];
#pragma unroll
    for (int c = 0; c < 5; c++) acc[c] = b2[c];
    for (int k = 0; k < 128; k++) {
        float xv = g_h2[k * N_TOT + n];
#pragma unroll
        for (int c = 0; c < 5; c++)
            acc[c] = fmaf(__ldg(&w2[c * 128 + k]), xv, acc[c]);
    }
#pragma unroll
    for (int c = 0; c < 5; c++) g_h3[c * N_TOT + n] = acc[c];
}

// ---------------- bilinear upsample x8 (align-corners grid) -> seg_pred ----------------
__global__ void upsample_k(float* __restrict__ out) {
    int idx = blockIdx.x * blockDim.x + threadIdx.x;
    if (idx >= SEG_ELEMS) return;
    int ow = idx % 800;
    int t  = idx / 800;
    int oh = t % 288; t /= 288;
    int c  = t % 5;
    int b  = t / 5;

    float fh = (float)oh * (35.0f / 287.0f);
    int   i0 = (int)fh; if (i0 > 34) i0 = 34;
    float ah = fh - (float)i0;
    float fw = (float)ow * (99.0f / 799.0f);
    int   j0 = (int)fw; if (j0 > 98) j0 = 98;
    float aw = fw - (float)j0;

    const float* src = g_h3 + c * N_TOT + b * 3600;
    float v00 = src[i0 * 100 + j0];
    float v01 = src[i0 * 100 + j0 + 1];
    float v10 = src[(i0 + 1) * 100 + j0];
    float v11 = src[(i0 + 1) * 100 + j0 + 1];
    float xh0 = v00 * (1.f - ah) + v10 * ah;
    float xh1 = v01 * (1.f - ah) + v11 * ah;
    out[idx] = xh0 * (1.f - aw) + xh1 * aw;
}

// ---------------- softmax over 5 channels + 2x2 avg pool -> g_p ----------------
__global__ void smpool_k() {
    int t = blockIdx.x * blockDim.x + threadIdx.x;
    if (t >= 8 * 18 * 50) return;
    int pw = t % 50;
    int r  = t / 50;
    int ph = r % 18;
    int b  = r / 18;

    float pc[5] = {0.f, 0.f, 0.f, 0.f, 0.f};
#pragma unroll
    for (int dh = 0; dh < 2; dh++)
#pragma unroll
        for (int dw = 0; dw < 2; dw++) {
            int h = 2 * ph + dh, w = 2 * pw + dw;
            const float* src = g_h3 + b * 3600 + h * 100 + w;
            float l[5];
#pragma unroll
            for (int c = 0; c < 5; c++) l[c] = src[c * N_TOT];
            float mx = l[0];
#pragma unroll
            for (int c = 1; c < 5; c++) mx = fmaxf(mx, l[c]);
            float s = 0.f;
#pragma unroll
            for (int c = 0; c < 5; c++) { l[c] = expf(l[c] - mx); s += l[c]; }
            float inv = 1.f / s;
#pragma unroll
            for (int c = 0; c < 5; c++) pc[c] += l[c] * inv;
        }
#pragma unroll
    for (int c = 0; c < 5; c++)
        g_p[b * 4500 + c * 900 + ph * 50 + pw] = pc[c] * 0.25f;
}

// ---------------- FC head: relu(fc1) -> sigmoid(fc2) -> exist_pred ----------------
__global__ void fc_k(const float* __restrict__ fc1w, const float* __restrict__ fc1b,
                     const float* __restrict__ fc2w, const float* __restrict__ fc2b,
                     float* __restrict__ out) {
    __shared__ float sf[128];
    int b = blockIdx.x;
    int c = threadIdx.x;
    const float* pb = g_p + b * 4500;
    float acc = fc1b[c];
    const float* wr = fc1w + c * 4500;
    for (int i = 0; i < 4500; i++)
        acc = fmaf(pb[i], wr[i], acc);
    sf[c] = fmaxf(acc, 0.f);
    __syncthreads();
    if (c < 4) {
        float a2 = fc2b[c];
#pragma unroll
        for (int k = 0; k < 128; k++)
            a2 = fmaf(sf[k], fc2w[c * 128 + k], a2);
        out[SEG_ELEMS + b * 4 + c] = 1.f / (1.f + expf(-a2));
    }
}

// ---------------- launch ----------------
extern "C" void kernel_launch(void* const* d_in, const int* in_sizes, int n_in,
                              void* d_out, int out_size) {
    const float* x    = (const float*)d_in[0];
    const float* w1a  = (const float*)d_in[1];
    const float* bn1g = (const float*)d_in[2];
    const float* bn1b = (const float*)d_in[3];
    const float* bn1m = (const float*)d_in[4];
    const float* bn1v = (const float*)d_in[5];
    const float* w1b  = (const float*)d_in[6];
    const float* bn2g = (const float*)d_in[7];
    const float* bn2b = (const float*)d_in[8];
    const float* bn2m = (const float*)d_in[9];
    const float* bn2v = (const float*)d_in[10];
    const float* wud  = (const float*)d_in[11];
    const float* wdu  = (const float*)d_in[12];
    const float* wlr  = (const float*)d_in[13];
    const float* wrl  = (const float*)d_in[14];
    const float* w2   = (const float*)d_in[15];
    const float* b2   = (const float*)d_in[16];
    const float* fc1w = (const float*)d_in[17];
    const float* fc1b = (const float*)d_in[18];
    const float* fc2w = (const float*)d_in[19];
    const float* fc2b = (const float*)d_in[20];
    float* out = (float*)d_out;

    // weight pack (reruns every call; deterministic)
    pack_w<<<(K1 * M1 + 255) / 256, 256>>>(w1a, w1b);

    // stage 1 + stage 2
    conv1a_k<<<dim3(225, 8), 256>>>(x, bn1g, bn1b, bn1m, bn1v);
    conv1b_k<<<dim3(225, 1), 256>>>(bn2g, bn2b, bn2m, bn2v);

    // message passing scans (sequential dependent steps)
    for (int i = 1; i < 36; i++)  step_w<<<dim3(8, 16), 256>>>(wud, i - 1, i);
    for (int i = 34; i >= 0; i--) step_w<<<dim3(8, 16), 256>>>(wdu, i + 1, i);
    for (int j = 1; j < 100; j++) step_h<<<dim3(8, 16), 128>>>(wlr, j - 1, j);
    for (int j = 98; j >= 0; j--) step_h<<<dim3(8, 16), 128>>>(wrl, j + 1, j);

    // head
    conv2_k<<<(N_TOT + 255) / 256, 256>>>(w2, b2);
    upsample_k<<<(SEG_ELEMS + 255) / 256, 256>>>(out);
    smpool_k<<<(8 * 18 * 50 + 255) / 256, 256>>>();
    fc_k<<<8, 128>>>(fc1w, fc1b, fc2w, fc2b, out);
}